// round 2
// baseline (speedup 1.0000x reference)
#include <cuda_runtime.h>
#include <cuda_bf16.h>

// Problem constants (from reference)
#define N_NODES 50000
#define N_REL   8
#define N_EDGES 64000
#define D       128            // D_IN == D_OUT == 128

// -------- scratch (static device globals; no runtime allocation) ----------
__device__ __align__(16) float g_agg[N_NODES * D];   // 25.6 MB, per-relation reuse
__device__ __align__(16) float g_odeg[N_NODES];      // counts -> inv-sqrt in place
__device__ __align__(16) float g_ideg[N_NODES];

// -------- helpers ----------------------------------------------------------
__device__ __forceinline__ void red_add_v4(float* p, float4 v) {
    asm volatile("red.global.add.v4.f32 [%0], {%1,%2,%3,%4};"
                 :: "l"(p), "f"(v.x), "f"(v.y), "f"(v.z), "f"(v.w)
                 : "memory");
}

// -------- kernels ----------------------------------------------------------

// zero d_out (poisoned by harness)
__global__ void zero_out_kernel(float4* out, int n4) {
    int i = blockIdx.x * blockDim.x + threadIdx.x;
    if (i < n4) out[i] = make_float4(0.f, 0.f, 0.f, 0.f);
}

// zero agg + both degree arrays (per relation)
__global__ void zero_scratch_kernel() {
    int i = blockIdx.x * blockDim.x + threadIdx.x;
    float4 z = make_float4(0.f, 0.f, 0.f, 0.f);
    if (i < (N_NODES * D / 4)) ((float4*)g_agg)[i] = z;
    if (i < (N_NODES / 4)) {
        ((float4*)g_odeg)[i] = z;
        ((float4*)g_ideg)[i] = z;
    }
}

// NOTE: edge indices are int32 on device (JAX x64 disabled downgrades int64)
__global__ void degree_kernel(const int* __restrict__ src,
                              const int* __restrict__ dst) {
    int e = blockIdx.x * blockDim.x + threadIdx.x;
    if (e < N_EDGES) {
        atomicAdd(&g_odeg[src[e]], 1.0f);
        atomicAdd(&g_ideg[dst[e]], 1.0f);
    }
}

__global__ void invdeg_kernel() {
    int i = blockIdx.x * blockDim.x + threadIdx.x;
    if (i < N_NODES) {
        g_odeg[i] = rsqrtf(fmaxf(g_odeg[i], 1.0f));
        g_ideg[i] = rsqrtf(fmaxf(g_ideg[i], 1.0f));
    }
}

// one warp per edge: gather feature row (scaled), red.add.v4 into agg[dst]
__global__ void scatter_kernel(const float* __restrict__ feat,
                               const int* __restrict__ src,
                               const int* __restrict__ dst) {
    int w    = (blockIdx.x * blockDim.x + threadIdx.x) >> 5;
    int lane = threadIdx.x & 31;
    if (w >= N_EDGES) return;
    int s = src[w];
    int d = dst[w];
    float sc = g_odeg[s];                         // outdeg^-1/2
    float4 v = ((const float4*)feat)[s * 32 + lane];
    v.x *= sc; v.y *= sc; v.z *= sc; v.w *= sc;
    red_add_v4(&g_agg[d * D + lane * 4], v);
}

// out[n,:] += (agg[n,:] @ W) * indeg_inv[n] + b
// W (128x128) resident in smem; 32-row tiles; 4 rows x 4 cols per thread.
#define GEMM_BLOCKS 296
#define GEMM_SMEM   ((16384 + 4096) * 4)

__global__ void __launch_bounds__(256, 2)
gemm_kernel(const float* __restrict__ W, const float* __restrict__ b,
            float* __restrict__ out) {
    extern __shared__ float smem[];
    float* sW = smem;             // 128 x 128
    float* sA = smem + 16384;     // 32 x 128

    int t = threadIdx.x;

    // load W into smem once per block
    const float4* W4 = (const float4*)W;
    float4* sW4 = (float4*)sW;
    #pragma unroll
    for (int i = 0; i < 16; i++) sW4[t + i * 256] = W4[t + i * 256];

    int cg = t & 31;     // column group: cols 4*cg .. 4*cg+3 (lane id)
    int rg = t >> 5;     // row group within tile: rows 4*rg .. 4*rg+3 (warp id)
    float4 bv = *(const float4*)(b + cg * 4);

    __syncthreads();

    const int numTiles = (N_NODES + 31) / 32;   // 1563
    for (int tile = blockIdx.x; tile < numTiles; tile += gridDim.x) {
        int row0 = tile * 32;

        // stage 32 agg rows
        float4* sA4 = (float4*)sA;
        #pragma unroll
        for (int i = 0; i < 4; i++) {
            int f   = t + i * 256;           // float4 index within tile
            int rr  = f >> 5;
            int kk  = f & 31;
            int row = row0 + rr;
            sA4[f] = (row < N_NODES) ? ((const float4*)g_agg)[row * 32 + kk]
                                     : make_float4(0.f, 0.f, 0.f, 0.f);
        }
        __syncthreads();

        float acc0x=0,acc0y=0,acc0z=0,acc0w=0;
        float acc1x=0,acc1y=0,acc1z=0,acc1w=0;
        float acc2x=0,acc2y=0,acc2z=0,acc2w=0;
        float acc3x=0,acc3y=0,acc3z=0,acc3w=0;

        const float* aBase = sA + rg * 4 * D;
        #pragma unroll 8
        for (int k = 0; k < D; k += 4) {
            float4 a0 = *(const float4*)(aBase + 0 * D + k);
            float4 a1 = *(const float4*)(aBase + 1 * D + k);
            float4 a2 = *(const float4*)(aBase + 2 * D + k);
            float4 a3 = *(const float4*)(aBase + 3 * D + k);
            float4 w0 = *(const float4*)(sW + (k + 0) * D + cg * 4);
            float4 w1 = *(const float4*)(sW + (k + 1) * D + cg * 4);
            float4 w2 = *(const float4*)(sW + (k + 2) * D + cg * 4);
            float4 w3 = *(const float4*)(sW + (k + 3) * D + cg * 4);

            acc0x = fmaf(a0.x, w0.x, acc0x); acc0y = fmaf(a0.x, w0.y, acc0y);
            acc0z = fmaf(a0.x, w0.z, acc0z); acc0w = fmaf(a0.x, w0.w, acc0w);
            acc0x = fmaf(a0.y, w1.x, acc0x); acc0y = fmaf(a0.y, w1.y, acc0y);
            acc0z = fmaf(a0.y, w1.z, acc0z); acc0w = fmaf(a0.y, w1.w, acc0w);
            acc0x = fmaf(a0.z, w2.x, acc0x); acc0y = fmaf(a0.z, w2.y, acc0y);
            acc0z = fmaf(a0.z, w2.z, acc0z); acc0w = fmaf(a0.z, w2.w, acc0w);
            acc0x = fmaf(a0.w, w3.x, acc0x); acc0y = fmaf(a0.w, w3.y, acc0y);
            acc0z = fmaf(a0.w, w3.z, acc0z); acc0w = fmaf(a0.w, w3.w, acc0w);

            acc1x = fmaf(a1.x, w0.x, acc1x); acc1y = fmaf(a1.x, w0.y, acc1y);
            acc1z = fmaf(a1.x, w0.z, acc1z); acc1w = fmaf(a1.x, w0.w, acc1w);
            acc1x = fmaf(a1.y, w1.x, acc1x); acc1y = fmaf(a1.y, w1.y, acc1y);
            acc1z = fmaf(a1.y, w1.z, acc1z); acc1w = fmaf(a1.y, w1.w, acc1w);
            acc1x = fmaf(a1.z, w2.x, acc1x); acc1y = fmaf(a1.z, w2.y, acc1y);
            acc1z = fmaf(a1.z, w2.z, acc1z); acc1w = fmaf(a1.z, w2.w, acc1w);
            acc1x = fmaf(a1.w, w3.x, acc1x); acc1y = fmaf(a1.w, w3.y, acc1y);
            acc1z = fmaf(a1.w, w3.z, acc1z); acc1w = fmaf(a1.w, w3.w, acc1w);

            acc2x = fmaf(a2.x, w0.x, acc2x); acc2y = fmaf(a2.x, w0.y, acc2y);
            acc2z = fmaf(a2.x, w0.z, acc2z); acc2w = fmaf(a2.x, w0.w, acc2w);
            acc2x = fmaf(a2.y, w1.x, acc2x); acc2y = fmaf(a2.y, w1.y, acc2y);
            acc2z = fmaf(a2.y, w1.z, acc2z); acc2w = fmaf(a2.y, w1.w, acc2w);
            acc2x = fmaf(a2.z, w2.x, acc2x); acc2y = fmaf(a2.z, w2.y, acc2y);
            acc2z = fmaf(a2.z, w2.z, acc2z); acc2w = fmaf(a2.z, w2.w, acc2w);
            acc2x = fmaf(a2.w, w3.x, acc2x); acc2y = fmaf(a2.w, w3.y, acc2y);
            acc2z = fmaf(a2.w, w3.z, acc2z); acc2w = fmaf(a2.w, w3.w, acc2w);

            acc3x = fmaf(a3.x, w0.x, acc3x); acc3y = fmaf(a3.x, w0.y, acc3y);
            acc3z = fmaf(a3.x, w0.z, acc3z); acc3w = fmaf(a3.x, w0.w, acc3w);
            acc3x = fmaf(a3.y, w1.x, acc3x); acc3y = fmaf(a3.y, w1.y, acc3y);
            acc3z = fmaf(a3.y, w1.z, acc3z); acc3w = fmaf(a3.y, w1.w, acc3w);
            acc3x = fmaf(a3.z, w2.x, acc3x); acc3y = fmaf(a3.z, w2.y, acc3y);
            acc3z = fmaf(a3.z, w2.z, acc3z); acc3w = fmaf(a3.z, w2.w, acc3w);
            acc3x = fmaf(a3.w, w3.x, acc3x); acc3y = fmaf(a3.w, w3.y, acc3y);
            acc3z = fmaf(a3.w, w3.z, acc3z); acc3w = fmaf(a3.w, w3.w, acc3w);
        }
        __syncthreads();   // sA consumed; safe to overwrite next tile

        // epilogue: out += acc * indeg_inv[row] + b
        {
            int row = row0 + rg * 4;
            if (row < N_NODES) {
                float s = g_ideg[row];
                float4* o = (float4*)(out + row * D + cg * 4);
                float4 ov = *o;
                ov.x += acc0x * s + bv.x; ov.y += acc0y * s + bv.y;
                ov.z += acc0z * s + bv.z; ov.w += acc0w * s + bv.w;
                *o = ov;
            }
            row++;
            if (row < N_NODES) {
                float s = g_ideg[row];
                float4* o = (float4*)(out + row * D + cg * 4);
                float4 ov = *o;
                ov.x += acc1x * s + bv.x; ov.y += acc1y * s + bv.y;
                ov.z += acc1z * s + bv.z; ov.w += acc1w * s + bv.w;
                *o = ov;
            }
            row++;
            if (row < N_NODES) {
                float s = g_ideg[row];
                float4* o = (float4*)(out + row * D + cg * 4);
                float4 ov = *o;
                ov.x += acc2x * s + bv.x; ov.y += acc2y * s + bv.y;
                ov.z += acc2z * s + bv.z; ov.w += acc2w * s + bv.w;
                *o = ov;
            }
            row++;
            if (row < N_NODES) {
                float s = g_ideg[row];
                float4* o = (float4*)(out + row * D + cg * 4);
                float4 ov = *o;
                ov.x += acc3x * s + bv.x; ov.y += acc3y * s + bv.y;
                ov.z += acc3z * s + bv.z; ov.w += acc3w * s + bv.w;
                *o = ov;
            }
        }
    }
}

// -------- launch -----------------------------------------------------------
extern "C" void kernel_launch(void* const* d_in, const int* in_sizes, int n_in,
                              void* d_out, int out_size) {
    const float* feat = (const float*)d_in[0];       // [50000,128] f32
    const float* W    = (const float*)d_in[1];       // [8,128,128] f32
    const float* b    = (const float*)d_in[2];       // [8,128]     f32
    const int*   src  = (const int*)d_in[3];         // [8,64000]   int32 (JAX x64 off)
    const int*   dst  = (const int*)d_in[4];         // [8,64000]   int32
    float* out = (float*)d_out;                      // [50000,128] f32

    cudaFuncSetAttribute(gemm_kernel,
                         cudaFuncAttributeMaxDynamicSharedMemorySize, GEMM_SMEM);

    const int n4_out = N_NODES * D / 4;              // 1.6M float4
    zero_out_kernel<<<(n4_out + 255) / 256, 256>>>((float4*)out, n4_out);

    for (int r = 0; r < N_REL; r++) {
        const int* sr = src + (size_t)r * N_EDGES;
        const int* dr = dst + (size_t)r * N_EDGES;

        zero_scratch_kernel<<<(n4_out + 255) / 256, 256>>>();
        degree_kernel<<<(N_EDGES + 255) / 256, 256>>>(sr, dr);
        invdeg_kernel<<<(N_NODES + 255) / 256, 256>>>();
        scatter_kernel<<<N_EDGES / 8, 256>>>(feat, sr, dr);   // 1 warp/edge
        gemm_kernel<<<GEMM_BLOCKS, 256, GEMM_SMEM>>>(
            W + (size_t)r * D * D, b + (size_t)r * D, out);
    }
}

// round 3
// speedup vs baseline: 1.1042x; 1.1042x over previous
#include <cuda_runtime.h>
#include <cuda_bf16.h>

#define N_NODES 50000
#define N_REL   8
#define N_EDGES 64000
#define D       128
#define NTOT    (N_REL * N_NODES)

// -------- scratch (static device globals; no runtime allocation) ----------
__device__ __align__(16) float g_agg[(size_t)N_REL * N_NODES * D];  // 204.8 MB
__device__ __align__(16) float g_odeg[NTOT];   // counts -> inv-sqrt in place
__device__ __align__(16) float g_ideg[NTOT];

__device__ __forceinline__ void red_add_v4(float* p, float4 v) {
    asm volatile("red.global.add.v4.f32 [%0], {%1,%2,%3,%4};"
                 :: "l"(p), "f"(v.x), "f"(v.y), "f"(v.z), "f"(v.w)
                 : "memory");
}

// -------- kernels ----------------------------------------------------------

// zero all agg buffers + degree arrays in one pass
__global__ void zero_all_kernel() {
    int i = blockIdx.x * blockDim.x + threadIdx.x;          // float4 index
    float4 z = make_float4(0.f, 0.f, 0.f, 0.f);
    if (i < (int)((size_t)N_REL * N_NODES * D / 4)) ((float4*)g_agg)[i] = z;
    if (i < NTOT / 4) {
        ((float4*)g_odeg)[i] = z;
        ((float4*)g_ideg)[i] = z;
    }
}

// all relations: blockIdx.y = r
__global__ void degree_kernel(const int* __restrict__ src,
                              const int* __restrict__ dst) {
    int e = blockIdx.x * blockDim.x + threadIdx.x;
    int r = blockIdx.y;
    if (e < N_EDGES) {
        atomicAdd(&g_odeg[r * N_NODES + src[r * N_EDGES + e]], 1.0f);
        atomicAdd(&g_ideg[r * N_NODES + dst[r * N_EDGES + e]], 1.0f);
    }
}

__global__ void invdeg_kernel() {
    int i = blockIdx.x * blockDim.x + threadIdx.x;
    if (i < NTOT) {
        g_odeg[i] = rsqrtf(fmaxf(g_odeg[i], 1.0f));
        g_ideg[i] = rsqrtf(fmaxf(g_ideg[i], 1.0f));
    }
}

// one warp per edge, all relations (blockIdx.y = r)
__global__ void scatter_kernel(const float* __restrict__ feat,
                               const int* __restrict__ src,
                               const int* __restrict__ dst) {
    int w    = (blockIdx.x * blockDim.x + threadIdx.x) >> 5;  // edge within rel
    int lane = threadIdx.x & 31;
    int r    = blockIdx.y;
    if (w >= N_EDGES) return;
    int s = src[r * N_EDGES + w];
    int d = dst[r * N_EDGES + w];
    float sc = g_odeg[r * N_NODES + s];                       // outdeg^-1/2
    float4 v = ((const float4*)feat)[s * 32 + lane];
    v.x *= sc; v.y *= sc; v.z *= sc; v.w *= sc;
    red_add_v4(&g_agg[(size_t)r * N_NODES * D + (size_t)d * D + lane * 4], v);
}

// out[n,:] = sum_r (ideg_r[n] * agg_r[n,:]) @ W_r + sum_r b_r
// 128x128 row tile per block, 256 threads, 8x8 microtile, acc persists over r.
#define GEMM_SMEM (2 * 128 * 128 * 4)   // sW + sA = 128 KB

__global__ void __launch_bounds__(256, 1)
gemm_all_kernel(const float* __restrict__ W, const float* __restrict__ b,
                float* __restrict__ out) {
    extern __shared__ float smem[];
    float4* sW4 = (float4*)smem;              // 128 x 128 (row = k, col = out)
    float4* sA4 = (float4*)(smem + 16384);    // 128 x 128 (row-major, prescaled)

    int t  = threadIdx.x;
    int tx = t & 15;          // col group: cols 8*tx .. 8*tx+7
    int ty = t >> 4;          // row group: rows 8*ty .. 8*ty+7
    int row0 = blockIdx.x * 128;

    // bias sum over relations for this thread's 8 columns
    float bs[8];
    #pragma unroll
    for (int c = 0; c < 8; c++) {
        float s = 0.f;
        #pragma unroll
        for (int r = 0; r < N_REL; r++) s += b[r * D + 8 * tx + c];
        bs[c] = s;
    }

    float acc[8][8];
    #pragma unroll
    for (int j = 0; j < 8; j++)
        #pragma unroll
        for (int c = 0; c < 8; c++) acc[j][c] = 0.f;

    for (int r = 0; r < N_REL; r++) {
        // stage W_r
        const float4* Wg = (const float4*)(W + (size_t)r * D * D);
        #pragma unroll
        for (int i = 0; i < 16; i++) sW4[t + i * 256] = Wg[t + i * 256];

        // stage A tile, prescaled by indeg^-1/2 (commutes with @W)
        const float4* Ag   = (const float4*)(g_agg + (size_t)r * N_NODES * D);
        const float*  ideg = g_ideg + r * N_NODES;
        #pragma unroll
        for (int i = 0; i < 16; i++) {
            int f   = t + i * 256;
            int rr  = f >> 5;
            int k4  = f & 31;
            int row = row0 + rr;
            float4 v = make_float4(0.f, 0.f, 0.f, 0.f);
            if (row < N_NODES) {
                v = Ag[(size_t)row * 32 + k4];
                float s = ideg[row];
                v.x *= s; v.y *= s; v.z *= s; v.w *= s;
            }
            sA4[f] = v;
        }
        __syncthreads();

        #pragma unroll 4
        for (int k4 = 0; k4 < 32; k4++) {
            float4 a[8];
            #pragma unroll
            for (int j = 0; j < 8; j++) a[j] = sA4[(8 * ty + j) * 32 + k4];

            #pragma unroll
            for (int kk = 0; kk < 4; kk++) {
                float4 wl = sW4[(4 * k4 + kk) * 32 + 2 * tx];
                float4 wh = sW4[(4 * k4 + kk) * 32 + 2 * tx + 1];
                #pragma unroll
                for (int j = 0; j < 8; j++) {
                    float av = (kk == 0) ? a[j].x : (kk == 1) ? a[j].y
                             : (kk == 2) ? a[j].z : a[j].w;
                    acc[j][0] = fmaf(av, wl.x, acc[j][0]);
                    acc[j][1] = fmaf(av, wl.y, acc[j][1]);
                    acc[j][2] = fmaf(av, wl.z, acc[j][2]);
                    acc[j][3] = fmaf(av, wl.w, acc[j][3]);
                    acc[j][4] = fmaf(av, wh.x, acc[j][4]);
                    acc[j][5] = fmaf(av, wh.y, acc[j][5]);
                    acc[j][6] = fmaf(av, wh.z, acc[j][6]);
                    acc[j][7] = fmaf(av, wh.w, acc[j][7]);
                }
            }
        }
        __syncthreads();   // tiles consumed; safe to restage next relation
    }

    // epilogue: single write of out
    #pragma unroll
    for (int j = 0; j < 8; j++) {
        int row = row0 + 8 * ty + j;
        if (row < N_NODES) {
            float4* o = (float4*)(out + (size_t)row * D + 8 * tx);
            o[0] = make_float4(acc[j][0] + bs[0], acc[j][1] + bs[1],
                               acc[j][2] + bs[2], acc[j][3] + bs[3]);
            o[1] = make_float4(acc[j][4] + bs[4], acc[j][5] + bs[5],
                               acc[j][6] + bs[6], acc[j][7] + bs[7]);
        }
    }
}

// -------- launch -----------------------------------------------------------
extern "C" void kernel_launch(void* const* d_in, const int* in_sizes, int n_in,
                              void* d_out, int out_size) {
    const float* feat = (const float*)d_in[0];   // [50000,128] f32
    const float* W    = (const float*)d_in[1];   // [8,128,128] f32
    const float* b    = (const float*)d_in[2];   // [8,128]     f32
    const int*   src  = (const int*)d_in[3];     // [8,64000]   int32
    const int*   dst  = (const int*)d_in[4];     // [8,64000]   int32
    float* out = (float*)d_out;                  // [50000,128] f32

    cudaFuncSetAttribute(gemm_all_kernel,
                         cudaFuncAttributeMaxDynamicSharedMemorySize, GEMM_SMEM);

    const int n4_agg = (int)((size_t)N_REL * N_NODES * D / 4);   // 12.8M float4
    zero_all_kernel<<<(n4_agg + 255) / 256, 256>>>();

    dim3 dgrid((N_EDGES + 255) / 256, N_REL);
    degree_kernel<<<dgrid, 256>>>(src, dst);

    invdeg_kernel<<<(NTOT + 255) / 256, 256>>>();

    dim3 sgrid(N_EDGES / 8, N_REL);              // 1 warp per edge
    scatter_kernel<<<sgrid, 256>>>(feat, src, dst);

    gemm_all_kernel<<<(N_NODES + 127) / 128, 256, GEMM_SMEM>>>(W, b, out);
}

// round 5
// speedup vs baseline: 1.8028x; 1.6326x over previous
#include <cuda_runtime.h>
#include <cuda_bf16.h>
#include <cstdint>

#define N_NODES 50000
#define N_REL   8
#define N_EDGES 64000
#define D       128
#define NTOT    (N_REL * N_NODES)

// -------- scratch (static device globals; no runtime allocation) ----------
__device__ __align__(16) float   g_agg[(size_t)N_REL * N_NODES * D];  // 204.8 MB
__device__ __align__(16) float   g_odeg[NTOT];
__device__ __align__(16) float   g_ideg[NTOT];
__device__ __align__(16) uint8_t g_wt_hi[N_REL * 32768];  // W^T bf16 hi, swizzled image
__device__ __align__(16) uint8_t g_wt_lo[N_REL * 32768];  // W^T bf16 lo, swizzled image

// -------- small helpers ----------------------------------------------------
__device__ __forceinline__ void red_add_v4(float* p, float4 v) {
    asm volatile("red.global.add.v4.f32 [%0], {%1,%2,%3,%4};"
                 :: "l"(p), "f"(v.x), "f"(v.y), "f"(v.z), "f"(v.w)
                 : "memory");
}

__device__ __forceinline__ uint32_t smem_u32(const void* p) {
    uint32_t a;
    asm("{ .reg .u64 t; cvta.to.shared.u64 t, %1; cvt.u32.u64 %0, t; }"
        : "=r"(a) : "l"(p));
    return a;
}

// smem image: row-major [128 rows][128 bf16], row stride 256B = 16 chunks of 16B.
// chunk swizzle: c' = c ^ (row & 7)  -> 8 consecutive rows at same c hit 8
// distinct 16B banks groups => conflict-free ldmatrix.
__device__ __forceinline__ uint32_t img_off(int row, int c) {
    return (uint32_t)row * 256u + (uint32_t)((c ^ (row & 7)) << 4);
}

// split two fp32 into packed bf16x2 hi + lo (residual)
__device__ __forceinline__ void split2(float a, float b, uint32_t& h, uint32_t& l) {
    __nv_bfloat16 ha = __float2bfloat16(a);
    __nv_bfloat16 hb = __float2bfloat16(b);
    __nv_bfloat16 la = __float2bfloat16(a - __bfloat162float(ha));
    __nv_bfloat16 lb = __float2bfloat16(b - __bfloat162float(hb));
    __nv_bfloat162 hp; hp.x = ha; hp.y = hb;
    __nv_bfloat162 lp; lp.x = la; lp.y = lb;
    h = *reinterpret_cast<uint32_t*>(&hp);
    l = *reinterpret_cast<uint32_t*>(&lp);
}

__device__ __forceinline__ void ldsm_x4(uint32_t addr, uint32_t& r0, uint32_t& r1,
                                        uint32_t& r2, uint32_t& r3) {
    asm volatile("ldmatrix.sync.aligned.m8n8.x4.shared.b16 {%0,%1,%2,%3}, [%4];"
                 : "=r"(r0), "=r"(r1), "=r"(r2), "=r"(r3) : "r"(addr));
}

__device__ __forceinline__ void mma_bf16(float& d0, float& d1, float& d2, float& d3,
                                         uint32_t a0, uint32_t a1, uint32_t a2,
                                         uint32_t a3, uint32_t b0, uint32_t b1) {
    asm volatile("mma.sync.aligned.m16n8k16.row.col.f32.bf16.bf16.f32 "
                 "{%0,%1,%2,%3}, {%4,%5,%6,%7}, {%8,%9}, {%0,%1,%2,%3};"
                 : "+f"(d0), "+f"(d1), "+f"(d2), "+f"(d3)
                 : "r"(a0), "r"(a1), "r"(a2), "r"(a3), "r"(b0), "r"(b1));
}

// -------- graph kernels -----------------------------------------------------
__global__ void zero_all_kernel() {
    int i = blockIdx.x * blockDim.x + threadIdx.x;
    float4 z = make_float4(0.f, 0.f, 0.f, 0.f);
    if (i < (int)((size_t)N_REL * N_NODES * D / 4)) ((float4*)g_agg)[i] = z;
    if (i < NTOT / 4) {
        ((float4*)g_odeg)[i] = z;
        ((float4*)g_ideg)[i] = z;
    }
}

__global__ void degree_kernel(const int* __restrict__ src,
                              const int* __restrict__ dst) {
    int e = blockIdx.x * blockDim.x + threadIdx.x;
    int r = blockIdx.y;
    if (e < N_EDGES) {
        atomicAdd(&g_odeg[r * N_NODES + src[r * N_EDGES + e]], 1.0f);
        atomicAdd(&g_ideg[r * N_NODES + dst[r * N_EDGES + e]], 1.0f);
    }
}

__global__ void invdeg_kernel() {
    int i = blockIdx.x * blockDim.x + threadIdx.x;
    if (i < NTOT) {
        g_odeg[i] = rsqrtf(fmaxf(g_odeg[i], 1.0f));
        g_ideg[i] = rsqrtf(fmaxf(g_ideg[i], 1.0f));
    }
}

__global__ void scatter_kernel(const float* __restrict__ feat,
                               const int* __restrict__ src,
                               const int* __restrict__ dst) {
    int w    = (blockIdx.x * blockDim.x + threadIdx.x) >> 5;
    int lane = threadIdx.x & 31;
    int r    = blockIdx.y;
    if (w >= N_EDGES) return;
    int s = src[r * N_EDGES + w];
    int d = dst[r * N_EDGES + w];
    float sc = g_odeg[r * N_NODES + s];
    float4 v = ((const float4*)feat)[s * 32 + lane];
    v.x *= sc; v.y *= sc; v.z *= sc; v.w *= sc;
    red_add_v4(&g_agg[(size_t)r * N_NODES * D + (size_t)d * D + lane * 4], v);
}

// -------- W prep: transpose + bf16 hi/lo split into swizzled image ---------
// One block per relation. Image row = n (out-col), chunks over k.
__global__ void prep_w_kernel(const float* __restrict__ W) {
    int r = blockIdx.x;
    int t = threadIdx.x;
    const float* Wr = W + (size_t)r * D * D;
    int n = t & 127;
    #pragma unroll
    for (int i = 0; i < 8; i++) {
        int seg = (t >> 7) + 2 * i;              // 0..15 (8 k's each)
        float v[8];
        #pragma unroll
        for (int j = 0; j < 8; j++)
            v[j] = Wr[(seg * 8 + j) * D + n];    // coalesced across lanes (n)
        uint4 hi, lo;
        split2(v[0], v[1], hi.x, lo.x);
        split2(v[2], v[3], hi.y, lo.y);
        split2(v[4], v[5], hi.z, lo.z);
        split2(v[6], v[7], hi.w, lo.w);
        uint32_t off = img_off(n, seg);
        *(uint4*)(g_wt_hi + r * 32768 + off) = hi;
        *(uint4*)(g_wt_lo + r * 32768 + off) = lo;
    }
}

// -------- mma.sync GEMM: out = sum_r (ideg_r ⊙ agg_r) @ W_r + sum_r b_r ----
#define OFF_A_HI 0
#define OFF_A_LO 32768
#define OFF_W_HI 65536
#define OFF_W_LO 98304
#define OFF_BIAS 131072
#define GEMM_SMEM 131584

__global__ void __launch_bounds__(256, 1)
gemm_mma_kernel(const float* __restrict__ b, float* __restrict__ out) {
    extern __shared__ char smem[];
    uint32_t sb = smem_u32(smem);
    int t = threadIdx.x, wid = t >> 5, lane = t & 31;
    int row0 = blockIdx.x * 128;

    int mw0 = (wid >> 2) * 64;      // warp m-origin: 0 or 64
    int nw0 = (wid & 3) * 32;       // warp n-origin: 0,32,64,96

    float* sBias = (float*)(smem + OFF_BIAS);
    if (t < 128) {
        float s = 0.f;
        #pragma unroll
        for (int r = 0; r < N_REL; r++) s += b[r * D + t];
        sBias[t] = s;
    }

    float acc[4][4][4];             // [mi][ni][frag]
    #pragma unroll
    for (int mi = 0; mi < 4; mi++)
        #pragma unroll
        for (int ni = 0; ni < 4; ni++)
            #pragma unroll
            for (int q = 0; q < 4; q++) acc[mi][ni][q] = 0.f;

    // per-lane ldmatrix address components (row_in_16 = lane&15, kc_sel = lane>>4)
    int lrow = lane & 15;
    int ksel = lane >> 4;

    for (int r = 0; r < N_REL; r++) {
        // ---- stage W image (straight copy, pre-swizzled) ----
        {
            const uint4* wh = (const uint4*)(g_wt_hi + r * 32768);
            const uint4* wl = (const uint4*)(g_wt_lo + r * 32768);
            uint4* swh = (uint4*)(smem + OFF_W_HI);
            uint4* swl = (uint4*)(smem + OFF_W_LO);
            #pragma unroll
            for (int i = 0; i < 8; i++) {
                swh[t + 256 * i] = wh[t + 256 * i];
                swl[t + 256 * i] = wl[t + 256 * i];
            }
        }
        // ---- stage A tile: fp32 -> ideg-scaled -> bf16 hi/lo, swizzled ----
        {
            const float4* Ag   = (const float4*)(g_agg + (size_t)r * N_NODES * D);
            const float*  ideg = g_ideg + r * N_NODES;
            #pragma unroll
            for (int i = 0; i < 8; i++) {
                int f   = t + 256 * i;
                int rr  = f >> 4;
                int seg = f & 15;
                int row = row0 + rr;
                float v[8];
                if (row < N_NODES) {
                    float sc = ideg[row];
                    float4 x0 = Ag[(size_t)row * 32 + seg * 2];
                    float4 x1 = Ag[(size_t)row * 32 + seg * 2 + 1];
                    v[0] = x0.x * sc; v[1] = x0.y * sc; v[2] = x0.z * sc; v[3] = x0.w * sc;
                    v[4] = x1.x * sc; v[5] = x1.y * sc; v[6] = x1.z * sc; v[7] = x1.w * sc;
                } else {
                    #pragma unroll
                    for (int j = 0; j < 8; j++) v[j] = 0.f;
                }
                uint4 hi, lo;
                split2(v[0], v[1], hi.x, lo.x);
                split2(v[2], v[3], hi.y, lo.y);
                split2(v[4], v[5], hi.z, lo.z);
                split2(v[6], v[7], hi.w, lo.w);
                uint32_t off = img_off(rr, seg);
                *(uint4*)(smem + OFF_A_HI + off) = hi;
                *(uint4*)(smem + OFF_A_LO + off) = lo;
            }
        }
        __syncthreads();

        // ---- compute: 8 k-steps of m16n8k16 ----
        #pragma unroll
        for (int ks = 0; ks < 8; ks++) {
            int kc = ks * 2 + ksel;

            uint32_t ah[4][4], al[4][4];
            #pragma unroll
            for (int mi = 0; mi < 4; mi++) {
                int row = mw0 + mi * 16 + lrow;
                uint32_t off = img_off(row, kc);
                ldsm_x4(sb + OFF_A_HI + off, ah[mi][0], ah[mi][1], ah[mi][2], ah[mi][3]);
                ldsm_x4(sb + OFF_A_LO + off, al[mi][0], al[mi][1], al[mi][2], al[mi][3]);
            }
            uint32_t bh[4][2], bl[4][2];
            #pragma unroll
            for (int nh = 0; nh < 2; nh++) {
                int row = nw0 + nh * 16 + lrow;
                uint32_t off = img_off(row, kc);
                uint32_t r0, r1, r2, r3;
                ldsm_x4(sb + OFF_W_HI + off, r0, r1, r2, r3);
                bh[2 * nh][0] = r0; bh[2 * nh + 1][0] = r1;
                bh[2 * nh][1] = r2; bh[2 * nh + 1][1] = r3;
                ldsm_x4(sb + OFF_W_LO + off, r0, r1, r2, r3);
                bl[2 * nh][0] = r0; bl[2 * nh + 1][0] = r1;
                bl[2 * nh][1] = r2; bl[2 * nh + 1][1] = r3;
            }
            #pragma unroll
            for (int mi = 0; mi < 4; mi++)
                #pragma unroll
                for (int ni = 0; ni < 4; ni++) {
                    float* d = acc[mi][ni];
                    mma_bf16(d[0], d[1], d[2], d[3],
                             ah[mi][0], ah[mi][1], ah[mi][2], ah[mi][3],
                             bh[ni][0], bh[ni][1]);
                    mma_bf16(d[0], d[1], d[2], d[3],
                             ah[mi][0], ah[mi][1], ah[mi][2], ah[mi][3],
                             bl[ni][0], bl[ni][1]);
                    mma_bf16(d[0], d[1], d[2], d[3],
                             al[mi][0], al[mi][1], al[mi][2], al[mi][3],
                             bh[ni][0], bh[ni][1]);
                }
        }
        __syncthreads();   // tiles consumed; safe to restage next relation
    }

    // ---- epilogue: acc + bias -> out (single write) ----
    int qr = lane >> 2;            // 0..7  (row within 8)
    int qc = (lane & 3) * 2;       // 0,2,4,6
    #pragma unroll
    for (int mi = 0; mi < 4; mi++) {
        #pragma unroll
        for (int ni = 0; ni < 4; ni++) {
            int c  = nw0 + ni * 8 + qc;
            float b0 = sBias[c], b1 = sBias[c + 1];
            int ra = row0 + mw0 + mi * 16 + qr;
            int rb = ra + 8;
            if (ra < N_NODES) {
                float2* o = (float2*)(out + (size_t)ra * D + c);
                *o = make_float2(acc[mi][ni][0] + b0, acc[mi][ni][1] + b1);
            }
            if (rb < N_NODES) {
                float2* o = (float2*)(out + (size_t)rb * D + c);
                *o = make_float2(acc[mi][ni][2] + b0, acc[mi][ni][3] + b1);
            }
        }
    }
}

// -------- launch -----------------------------------------------------------
extern "C" void kernel_launch(void* const* d_in, const int* in_sizes, int n_in,
                              void* d_out, int out_size) {
    const float* feat = (const float*)d_in[0];   // [50000,128] f32
    const float* W    = (const float*)d_in[1];   // [8,128,128] f32
    const float* b    = (const float*)d_in[2];   // [8,128]     f32
    const int*   src  = (const int*)d_in[3];     // [8,64000]   int32
    const int*   dst  = (const int*)d_in[4];     // [8,64000]   int32
    float* out = (float*)d_out;                  // [50000,128] f32

    cudaFuncSetAttribute(gemm_mma_kernel,
                         cudaFuncAttributeMaxDynamicSharedMemorySize, GEMM_SMEM);

    const int n4_agg = (int)((size_t)N_REL * N_NODES * D / 4);
    zero_all_kernel<<<(n4_agg + 255) / 256, 256>>>();

    prep_w_kernel<<<N_REL, 256>>>(W);

    dim3 dgrid((N_EDGES + 255) / 256, N_REL);
    degree_kernel<<<dgrid, 256>>>(src, dst);

    invdeg_kernel<<<(NTOT + 255) / 256, 256>>>();

    dim3 sgrid(N_EDGES / 8, N_REL);
    scatter_kernel<<<sgrid, 256>>>(feat, src, dst);

    gemm_mma_kernel<<<(N_NODES + 127) / 128, 256, GEMM_SMEM>>>(b, out);
}

// round 7
// speedup vs baseline: 1.8667x; 1.0355x over previous
#include <cuda_runtime.h>
#include <cuda_bf16.h>
#include <cstdint>

#define N_NODES 50000
#define N_PAD   50048              // 391 * 128
#define N_TILES 391
#define N_REL   8
#define N_EDGES 64000
#define D       128
#define NTOT    (N_REL * N_NODES)

// -------- scratch (static device globals; no runtime allocation) ----------
__device__ __align__(16) float   g_Y[(size_t)N_REL * N_PAD * D];      // 205 MB
__device__ __align__(16) float   g_odeg[NTOT];
__device__ __align__(16) float   g_ideg[NTOT];
__device__ __align__(16) uint8_t g_ft_hi[N_TILES * 32768];            // feat bf16 hi image
__device__ __align__(16) uint8_t g_ft_lo[N_TILES * 32768];            // feat bf16 lo image
__device__ __align__(16) uint8_t g_wt_hi[N_REL * 32768];              // W^T bf16 hi image
__device__ __align__(16) uint8_t g_wt_lo[N_REL * 32768];              // W^T bf16 lo image

// -------- small helpers ----------------------------------------------------
__device__ __forceinline__ void red_add_v4(float* p, float4 v) {
    asm volatile("red.global.add.v4.f32 [%0], {%1,%2,%3,%4};"
                 :: "l"(p), "f"(v.x), "f"(v.y), "f"(v.z), "f"(v.w)
                 : "memory");
}

__device__ __forceinline__ uint32_t smem_u32(const void* p) {
    uint32_t a;
    asm("{ .reg .u64 t; cvta.to.shared.u64 t, %1; cvt.u32.u64 %0, t; }"
        : "=r"(a) : "l"(p));
    return a;
}

__device__ __forceinline__ void cp_async16(uint32_t saddr, const void* g) {
    asm volatile("cp.async.cg.shared.global [%0], [%1], 16;"
                 :: "r"(saddr), "l"(g) : "memory");
}
#define CP_COMMIT() asm volatile("cp.async.commit_group;" ::: "memory")
#define CP_WAIT(n)  asm volatile("cp.async.wait_group %0;" :: "n"(n) : "memory")

// smem/gmem image: row-major [128 rows][128 bf16], row stride 256B = 16 x 16B chunks.
// chunk swizzle c' = c ^ (row & 7) -> conflict-free ldmatrix.
__device__ __forceinline__ uint32_t img_off(int row, int c) {
    return (uint32_t)row * 256u + (uint32_t)((c ^ (row & 7)) << 4);
}

__device__ __forceinline__ void split2(float a, float b, uint32_t& h, uint32_t& l) {
    __nv_bfloat16 ha = __float2bfloat16(a);
    __nv_bfloat16 hb = __float2bfloat16(b);
    __nv_bfloat16 la = __float2bfloat16(a - __bfloat162float(ha));
    __nv_bfloat16 lb = __float2bfloat16(b - __bfloat162float(hb));
    __nv_bfloat162 hp; hp.x = ha; hp.y = hb;
    __nv_bfloat162 lp; lp.x = la; lp.y = lb;
    h = *reinterpret_cast<uint32_t*>(&hp);
    l = *reinterpret_cast<uint32_t*>(&lp);
}

__device__ __forceinline__ void ldsm_x4(uint32_t addr, uint32_t& r0, uint32_t& r1,
                                        uint32_t& r2, uint32_t& r3) {
    asm volatile("ldmatrix.sync.aligned.m8n8.x4.shared.b16 {%0,%1,%2,%3}, [%4];"
                 : "=r"(r0), "=r"(r1), "=r"(r2), "=r"(r3) : "r"(addr));
}

__device__ __forceinline__ void mma_bf16(float& d0, float& d1, float& d2, float& d3,
                                         uint32_t a0, uint32_t a1, uint32_t a2,
                                         uint32_t a3, uint32_t b0, uint32_t b1) {
    asm volatile("mma.sync.aligned.m16n8k16.row.col.f32.bf16.bf16.f32 "
                 "{%0,%1,%2,%3}, {%4,%5,%6,%7}, {%8,%9}, {%0,%1,%2,%3};"
                 : "+f"(d0), "+f"(d1), "+f"(d2), "+f"(d3)
                 : "r"(a0), "r"(a1), "r"(a2), "r"(a3), "r"(b0), "r"(b1));
}

// -------- prep / degree kernels --------------------------------------------
__global__ void zero_deg_kernel() {
    int i = blockIdx.x * blockDim.x + threadIdx.x;
    float4 z = make_float4(0.f, 0.f, 0.f, 0.f);
    if (i < NTOT / 4) {
        ((float4*)g_odeg)[i] = z;
        ((float4*)g_ideg)[i] = z;
    }
}

__global__ void degree_kernel(const int* __restrict__ src,
                              const int* __restrict__ dst) {
    int e = blockIdx.x * blockDim.x + threadIdx.x;
    int r = blockIdx.y;
    if (e < N_EDGES) {
        atomicAdd(&g_odeg[r * N_NODES + src[r * N_EDGES + e]], 1.0f);
        atomicAdd(&g_ideg[r * N_NODES + dst[r * N_EDGES + e]], 1.0f);
    }
}

__global__ void invdeg_kernel() {
    int i = blockIdx.x * blockDim.x + threadIdx.x;
    if (i < NTOT) {
        g_odeg[i] = rsqrtf(fmaxf(g_odeg[i], 1.0f));
        g_ideg[i] = rsqrtf(fmaxf(g_ideg[i], 1.0f));
    }
}

// out[n,c] = sum_r b[r][c]
__global__ void init_out_kernel(const float* __restrict__ b, float* __restrict__ out) {
    int i = blockIdx.x * blockDim.x + threadIdx.x;      // float4 index
    if (i >= N_NODES * D / 4) return;
    int c = (i & 31) * 4;
    float4 v = make_float4(0.f, 0.f, 0.f, 0.f);
    #pragma unroll
    for (int r = 0; r < N_REL; r++) {
        v.x += b[r * D + c];     v.y += b[r * D + c + 1];
        v.z += b[r * D + c + 2]; v.w += b[r * D + c + 3];
    }
    ((float4*)out)[i] = v;
}

// feat -> bf16 hi/lo swizzled tile images (once)
__global__ void prep_feat_kernel(const float* __restrict__ feat) {
    int ti = blockIdx.x;
    int t  = threadIdx.x;
    int row0 = ti * 128;
    #pragma unroll
    for (int i = 0; i < 8; i++) {
        int f   = t + 256 * i;
        int rr  = f >> 4;
        int seg = f & 15;
        int row = row0 + rr;
        float v[8];
        if (row < N_NODES) {
            float4 x0 = ((const float4*)feat)[(size_t)row * 32 + seg * 2];
            float4 x1 = ((const float4*)feat)[(size_t)row * 32 + seg * 2 + 1];
            v[0] = x0.x; v[1] = x0.y; v[2] = x0.z; v[3] = x0.w;
            v[4] = x1.x; v[5] = x1.y; v[6] = x1.z; v[7] = x1.w;
        } else {
            #pragma unroll
            for (int j = 0; j < 8; j++) v[j] = 0.f;
        }
        uint4 hi, lo;
        split2(v[0], v[1], hi.x, lo.x);
        split2(v[2], v[3], hi.y, lo.y);
        split2(v[4], v[5], hi.z, lo.z);
        split2(v[6], v[7], hi.w, lo.w);
        uint32_t off = img_off(rr, seg);
        *(uint4*)(g_ft_hi + (size_t)ti * 32768 + off) = hi;
        *(uint4*)(g_ft_lo + (size_t)ti * 32768 + off) = lo;
    }
}

// W -> transposed bf16 hi/lo swizzled images (once)
__global__ void prep_w_kernel(const float* __restrict__ W) {
    int r = blockIdx.x;
    int t = threadIdx.x;
    const float* Wr = W + (size_t)r * D * D;
    int n = t & 127;
    #pragma unroll
    for (int i = 0; i < 8; i++) {
        int seg = (t >> 7) + 2 * i;
        float v[8];
        #pragma unroll
        for (int j = 0; j < 8; j++)
            v[j] = Wr[(seg * 8 + j) * D + n];
        uint4 hi, lo;
        split2(v[0], v[1], hi.x, lo.x);
        split2(v[2], v[3], hi.y, lo.y);
        split2(v[4], v[5], hi.z, lo.z);
        split2(v[6], v[7], hi.w, lo.w);
        uint32_t off = img_off(n, seg);
        *(uint4*)(g_wt_hi + r * 32768 + off) = hi;
        *(uint4*)(g_wt_lo + r * 32768 + off) = lo;
    }
}

// -------- GEMM: Y_r = feat @ W_r for all r, A staged once ------------------
#define OFF_A_HI  0
#define OFF_A_LO  32768
#define OFF_W     65536            // two 64KB W buffers (hi 32KB + lo 32KB each)
#define GEMM_SMEM (65536 + 2 * 65536)

__global__ void __launch_bounds__(256, 1)
gemm_y_kernel() {
    extern __shared__ char smem[];
    uint32_t sb = smem_u32(smem);
    int t = threadIdx.x, wid = t >> 5, lane = t & 31;
    int ti = blockIdx.x;
    int row0 = ti * 128;

    int mw0 = (wid >> 2) * 64;
    int nw0 = (wid & 3) * 32;
    int lrow = lane & 15;
    int ksel = lane >> 4;

    // stage A + W_0 (group 0)
    {
        const uint8_t* ah = g_ft_hi + (size_t)ti * 32768;
        const uint8_t* al = g_ft_lo + (size_t)ti * 32768;
        #pragma unroll
        for (int i = 0; i < 8; i++) {
            uint32_t o = (uint32_t)(t + 256 * i) * 16;   // 0..32752
            cp_async16(sb + OFF_A_HI + o, ah + o);
            cp_async16(sb + OFF_A_LO + o, al + o);
            cp_async16(sb + OFF_W + o,           g_wt_hi + o);
            cp_async16(sb + OFF_W + 32768u + o,  g_wt_lo + o);
        }
    }
    CP_COMMIT();

    for (int r = 0; r < N_REL; r++) {
        int cur = r & 1;
        if (r + 1 < N_REL) {
            uint32_t wbase = OFF_W + (uint32_t)((r + 1) & 1) * 65536u;
            const uint8_t* wh = g_wt_hi + (r + 1) * 32768;
            const uint8_t* wl = g_wt_lo + (r + 1) * 32768;
            #pragma unroll
            for (int i = 0; i < 8; i++) {
                uint32_t o = (uint32_t)(t + 256 * i) * 16;
                cp_async16(sb + wbase + o,          wh + o);
                cp_async16(sb + wbase + 32768u + o, wl + o);
            }
            CP_COMMIT();
            CP_WAIT(1);
        } else {
            CP_WAIT(0);
        }
        __syncthreads();

        uint32_t wHi = sb + OFF_W + (uint32_t)cur * 65536u;
        uint32_t wLo = wHi + 32768u;

        float acc[4][4][4];
        #pragma unroll
        for (int mi = 0; mi < 4; mi++)
            #pragma unroll
            for (int ni = 0; ni < 4; ni++)
                #pragma unroll
                for (int q = 0; q < 4; q++) acc[mi][ni][q] = 0.f;

        #pragma unroll
        for (int ks = 0; ks < 8; ks++) {
            int kc = ks * 2 + ksel;
            uint32_t ah[4][4], al[4][4];
            #pragma unroll
            for (int mi = 0; mi < 4; mi++) {
                uint32_t off = img_off(mw0 + mi * 16 + lrow, kc);
                ldsm_x4(sb + OFF_A_HI + off, ah[mi][0], ah[mi][1], ah[mi][2], ah[mi][3]);
                ldsm_x4(sb + OFF_A_LO + off, al[mi][0], al[mi][1], al[mi][2], al[mi][3]);
            }
            uint32_t bh[4][2], bl[4][2];
            #pragma unroll
            for (int nh = 0; nh < 2; nh++) {
                uint32_t off = img_off(nw0 + nh * 16 + lrow, kc);
                uint32_t r0, r1, r2, r3;
                ldsm_x4(wHi + off, r0, r1, r2, r3);
                bh[2 * nh][0] = r0; bh[2 * nh + 1][0] = r1;
                bh[2 * nh][1] = r2; bh[2 * nh + 1][1] = r3;
                ldsm_x4(wLo + off, r0, r1, r2, r3);
                bl[2 * nh][0] = r0; bl[2 * nh + 1][0] = r1;
                bl[2 * nh][1] = r2; bl[2 * nh + 1][1] = r3;
            }
            #pragma unroll
            for (int mi = 0; mi < 4; mi++)
                #pragma unroll
                for (int ni = 0; ni < 4; ni++) {
                    float* d = acc[mi][ni];
                    mma_bf16(d[0], d[1], d[2], d[3],
                             ah[mi][0], ah[mi][1], ah[mi][2], ah[mi][3],
                             bh[ni][0], bh[ni][1]);
                    mma_bf16(d[0], d[1], d[2], d[3],
                             ah[mi][0], ah[mi][1], ah[mi][2], ah[mi][3],
                             bl[ni][0], bl[ni][1]);
                    mma_bf16(d[0], d[1], d[2], d[3],
                             al[mi][0], al[mi][1], al[mi][2], al[mi][3],
                             bh[ni][0], bh[ni][1]);
                }
        }

        // write Y_r tile (rows padded; pad rows hold zeros, never gathered)
        float* Yr = g_Y + (size_t)r * N_PAD * D;
        int qr = lane >> 2;
        int qc = (lane & 3) * 2;
        #pragma unroll
        for (int mi = 0; mi < 4; mi++)
            #pragma unroll
            for (int ni = 0; ni < 4; ni++) {
                int c  = nw0 + ni * 8 + qc;
                int ra = row0 + mw0 + mi * 16 + qr;
                float2* o0 = (float2*)(Yr + (size_t)ra * D + c);
                float2* o1 = (float2*)(Yr + (size_t)(ra + 8) * D + c);
                *o0 = make_float2(acc[mi][ni][0], acc[mi][ni][1]);
                *o1 = make_float2(acc[mi][ni][2], acc[mi][ni][3]);
            }
        __syncthreads();   // W buffer consumed; safe for next prefetch round
    }
}

// -------- scatter: out[d] += odeg[s]*ideg[d] * Y_r[s] ----------------------
__global__ void scatter_kernel(const int* __restrict__ src,
                               const int* __restrict__ dst,
                               float* __restrict__ out) {
    int w    = (blockIdx.x * blockDim.x + threadIdx.x) >> 5;
    int lane = threadIdx.x & 31;
    int r    = blockIdx.y;
    if (w >= N_EDGES) return;
    int s = src[r * N_EDGES + w];
    int d = dst[r * N_EDGES + w];
    float sc = g_odeg[r * N_NODES + s] * g_ideg[r * N_NODES + d];
    const float4* Yr = (const float4*)(g_Y + (size_t)r * N_PAD * D);
    float4 v = Yr[(size_t)s * 32 + lane];
    v.x *= sc; v.y *= sc; v.z *= sc; v.w *= sc;
    red_add_v4(&out[(size_t)d * D + lane * 4], v);
}

// -------- launch -----------------------------------------------------------
extern "C" void kernel_launch(void* const* d_in, const int* in_sizes, int n_in,
                              void* d_out, int out_size) {
    const float* feat = (const float*)d_in[0];   // [50000,128] f32
    const float* W    = (const float*)d_in[1];   // [8,128,128] f32
    const float* b    = (const float*)d_in[2];   // [8,128]     f32
    const int*   src  = (const int*)d_in[3];     // [8,64000]   int32
    const int*   dst  = (const int*)d_in[4];     // [8,64000]   int32
    float* out = (float*)d_out;                  // [50000,128] f32

    cudaFuncSetAttribute(gemm_y_kernel,
                         cudaFuncAttributeMaxDynamicSharedMemorySize, GEMM_SMEM);

    init_out_kernel<<<(N_NODES * D / 4 + 255) / 256, 256>>>(b, out);
    prep_feat_kernel<<<N_TILES, 256>>>(feat);
    prep_w_kernel<<<N_REL, 256>>>(W);

    zero_deg_kernel<<<(NTOT / 4 + 255) / 256, 256>>>();
    dim3 dgrid((N_EDGES + 255) / 256, N_REL);
    degree_kernel<<<dgrid, 256>>>(src, dst);
    invdeg_kernel<<<(NTOT + 255) / 256, 256>>>();

    gemm_y_kernel<<<N_TILES, 256, GEMM_SMEM>>>();

    dim3 sgrid(N_EDGES / 8, N_REL);
    scatter_kernel<<<sgrid, 256>>>(src, dst, out);
}